// round 4
// baseline (speedup 1.0000x reference)
#include <cuda_runtime.h>
#include <cstdint>
#include <cub/block/block_radix_sort.cuh>

// CutOutput: per-row (P*T = 8192 rows) stable descending argsort of D=1571
// fp32 scores; out[row][r] = (float)index_at_rank_r if r < len else 0,
// len = base[row] (ids = repeat(arange(P), T) -> visit (p,t) == row p*T+t).
// Output dtype is float32 (established round 3).
//
// Round-4 tuning (L1/smem-bound per ncu: L1=91.7%, DRAM=3.2%):
//  * 320 threads x 5 items = 1600 slots (was 1792): -10.7% per-item work.
//  * RADIX_BITS=5 -> 7 digit passes (was 8): -12.5% pass-proportional traffic.
//  * Stable LSD radix + blocked load order == ascending-index tie-break ==
//    JAX stable argsort semantics (required: fp32 ties do occur).

static constexpr int D = 1571;
static constexpr int THREADS = 320;
static constexpr int ITEMS = 5;   // 320*5 = 1600 >= 1571
static constexpr int RBITS = 5;   // ceil(32/5) = 7 passes

__global__ void __launch_bounds__(THREADS) cutoutput_radix_kernel(
    const float* __restrict__ to_cut,
    const int* __restrict__ candA,
    const int* __restrict__ candB,
    float* __restrict__ out) {
  using Sorter = cub::BlockRadixSort<unsigned int, THREADS, ITEMS,
                                     unsigned short, RBITS>;
  __shared__ typename Sorter::TempStorage tmp;

  const int row = blockIdx.x;
  const float* __restrict__ src = to_cut + (size_t)row * D;
  const int t = threadIdx.x;

  unsigned int keys[ITEMS];
  unsigned short vals[ITEMS];

  // Blocked load: thread t owns original positions [t*ITEMS, t*ITEMS+ITEMS).
#pragma unroll
  for (int i = 0; i < ITEMS; ++i) {
    const int v = t * ITEMS + i;
    unsigned int kk = 0xFFFFFFFFu;  // padding sorts strictly last
    if (v < D) {
      const unsigned int u = __float_as_uint(src[v]);
      const unsigned int a =
          u ^ ((u & 0x80000000u) ? 0xFFFFFFFFu : 0x80000000u);
      kk = ~a;  // ascending kk == descending float value
    }
    keys[i] = kk;
    vals[i] = (unsigned short)v;
  }

  Sorter(tmp).SortBlockedToStriped(keys, vals);

  // base vs ids disambiguation: ids[0] == 0 always; base[0] >= 1 always.
  const int* __restrict__ basep = (candA[0] == 0) ? candB : candA;
  const int len = basep[row];

  // Striped output: item i of thread t holds rank r = i*THREADS + t -> coalesced.
  float* __restrict__ dst = out + (size_t)row * D;
#pragma unroll
  for (int i = 0; i < ITEMS; ++i) {
    const int r = i * THREADS + t;
    if (r < D) dst[r] = (r < len) ? (float)vals[i] : 0.0f;
  }
}

extern "C" void kernel_launch(void* const* d_in, const int* in_sizes, int n_in,
                              void* d_out, int out_size) {
  // to_cut is the (unique) large buffer: P*T*D elements.
  int imax = 0;
  for (int i = 1; i < n_in; ++i)
    if (in_sizes[i] > in_sizes[imax]) imax = i;
  const float* to_cut = (const float*)d_in[imax];

  int others[2], k = 0;
  for (int i = 0; i < n_in && k < 2; ++i)
    if (i != imax) others[k++] = i;
  const int* candA = (const int*)d_in[others[0]];
  const int* candB = (const int*)d_in[others[1]];

  float* out = (float*)d_out;
  const int rows = in_sizes[imax] / D;  // P*T = 8192

  cutoutput_radix_kernel<<<rows, THREADS>>>(to_cut, candA, candB, out);
}

// round 5
// speedup vs baseline: 1.6837x; 1.6837x over previous
#include <cuda_runtime.h>
#include <cstdint>

// CutOutput: per-row (8192 rows) stable descending argsort of D=1571 fp32,
// out[row][r] = (float)index_at_rank_r if r < len else 0, len = base[row].
// Output dtype float32 (established R3). Stability required (fp32 ties exist).
//
// R5: single-pass distribution sort (replaces 8-pass cub radix, ~2.5x less
// smem traffic):
//   kk = ~flip(float_bits): ascending kk == descending value.
//   bucket = exact-monotone integer map: e = kk>>23 (octave), linear
//   interpolation on 16 mantissa bits between base[e], base[e+1];
//   base[] built per block from the N(0,1) CDF (erfcf) -> ~3 elems/bucket.
//   Phase 2: per-bucket rank by comparison counting on packed u64
//   (kk<<11 | idx): unique keys -> deterministic, idx tie-break == JAX stable.

static constexpr int D = 1571;
static constexpr int NB = 512;
static constexpr int THREADS = 512;

__global__ void __launch_bounds__(THREADS) cutoutput_bucket_kernel(
    const float* __restrict__ to_cut,
    const int* __restrict__ candA,
    const int* __restrict__ candB,
    float* __restrict__ out) {
  __shared__ unsigned long long data[D];     // bucketed (kk<<11)|idx
  __shared__ unsigned base[NB + 1];          // bucket-map table
  __shared__ unsigned startb[NB + 1];        // bucket start offsets
  __shared__ unsigned hist[NB];              // counts
  __shared__ unsigned cursor[NB];            // scatter cursors
  __shared__ unsigned wsum[16];              // scan partials
  __shared__ unsigned short staged[D];       // rank -> idx

  const int t = threadIdx.x;
  const int row = blockIdx.x;
  const float* __restrict__ src = to_cut + (size_t)row * D;

  // ---- build base[]: base[e] = floor(NB * P(value > band_edge(e))) ----
  {
    const unsigned kk0 = (unsigned)t << 23;      // lower edge of band t
    const unsigned a = ~kk0;
    const unsigned u = (a & 0x80000000u) ? (a ^ 0x80000000u) : ~a;
    const float x = __uint_as_float(u);          // band edge value (+/-inf ok)
    const float c = 0.5f * erfcf(x * 0.70710678118f);  // P(N(0,1) > x)
    unsigned b = (unsigned)(c * (float)NB);
    base[t] = b > (NB - 1u) ? (NB - 1u) : b;
    if (t == 0) base[NB] = NB;
    hist[t] = 0;
  }
  __syncthreads();

  // ---- phase 1: load, key, bucket, histogram ----
  unsigned kks[4];
  unsigned short bks[4];
#pragma unroll
  for (int k = 0; k < 4; ++k) {
    const int v = t + k * THREADS;
    if (v < D) {
      const unsigned u = __float_as_uint(src[v]);
      const unsigned a = u ^ ((u & 0x80000000u) ? 0xFFFFFFFFu : 0x80000000u);
      const unsigned kk = ~a;                     // ascending kk == desc value
      const unsigned e = kk >> 23;
      const unsigned b0 = base[e];
      const unsigned n = base[e + 1] - b0;
      const unsigned m = (kk >> 7) & 0xFFFFu;
      const unsigned bk = b0 + ((m * n) >> 16);   // exact monotone in kk
      kks[k] = kk;
      bks[k] = (unsigned short)bk;
      atomicAdd(&hist[bk], 1u);
    }
  }
  __syncthreads();

  // ---- exclusive scan of hist (512 threads, shfl + combine) ----
  {
    const unsigned cntv = hist[t];
    unsigned v = cntv;
#pragma unroll
    for (int d = 1; d < 32; d <<= 1) {
      unsigned nbr = __shfl_up_sync(0xFFFFFFFFu, v, d);
      if ((t & 31) >= d) v += nbr;
    }
    if ((t & 31) == 31) wsum[t >> 5] = v;
    __syncthreads();
    if (t < 16) {
      unsigned w = wsum[t];
#pragma unroll
      for (int d = 1; d < 16; d <<= 1) {
        unsigned nbr = __shfl_up_sync(0xFFFFu, w, d);
        if (t >= d) w += nbr;
      }
      wsum[t] = w;
    }
    __syncthreads();
    const unsigned excl =
        v - cntv + ((t >= 32) ? wsum[(t >> 5) - 1] : 0u);
    startb[t] = excl;
    cursor[t] = excl;
    if (t == 0) startb[NB] = (unsigned)D;
  }
  __syncthreads();

  // ---- scatter packed keys into bucket regions ----
#pragma unroll
  for (int k = 0; k < 4; ++k) {
    const int v = t + k * THREADS;
    if (v < D) {
      const unsigned pos = atomicAdd(&cursor[bks[k]], 1u);
      data[pos] = ((unsigned long long)kks[k] << 11) | (unsigned)v;
    }
  }
  __syncthreads();

  // ---- phase 2: rank within bucket by comparison counting ----
  {
    const unsigned s = startb[t];
    const unsigned e = startb[t + 1];
    for (unsigned i = s; i < e; ++i) {
      const unsigned long long ki = data[i];
      unsigned r = s;
      for (unsigned j = s; j < e; ++j) r += (data[j] < ki) ? 1u : 0u;
      staged[r] = (unsigned short)(ki & 0x7FFull);
    }
  }
  __syncthreads();

  // ---- output: coalesced sweep with len mask ----
  // base vs ids disambiguation: ids[0] == 0 always; base[0] >= 1 always.
  const int* __restrict__ basep = (candA[0] == 0) ? candB : candA;
  const int len = basep[row];
  float* __restrict__ dst = out + (size_t)row * D;
#pragma unroll
  for (int k = 0; k < 4; ++k) {
    const int r = t + k * THREADS;
    if (r < D) dst[r] = (r < len) ? (float)staged[r] : 0.0f;
  }
}

extern "C" void kernel_launch(void* const* d_in, const int* in_sizes, int n_in,
                              void* d_out, int out_size) {
  // to_cut is the (unique) large buffer: P*T*D elements.
  int imax = 0;
  for (int i = 1; i < n_in; ++i)
    if (in_sizes[i] > in_sizes[imax]) imax = i;
  const float* to_cut = (const float*)d_in[imax];

  int others[2], k = 0;
  for (int i = 0; i < n_in && k < 2; ++i)
    if (i != imax) others[k++] = i;
  const int* candA = (const int*)d_in[others[0]];
  const int* candB = (const int*)d_in[others[1]];

  float* out = (float*)d_out;
  const int rows = in_sizes[imax] / D;  // P*T = 8192

  cutoutput_bucket_kernel<<<rows, THREADS>>>(to_cut, candA, candB, out);
}

// round 6
// speedup vs baseline: 2.8280x; 1.6796x over previous
#include <cuda_runtime.h>
#include <cstdint>

// CutOutput: per-row (8192 rows) stable descending argsort of D=1571 fp32,
// out[row][r] = (float)index_at_rank_r if r < len else 0, len = base[row].
// Output float32. Stability required (fp32 ties -> packed-u64 idx tie-break).
//
// R6 (issue/ALU-bound per ncu): 1024 buckets (mean 1.53 elems), per-ELEMENT
// ranking (no per-bucket outer loop; own key stays in register), and the
// N(0,1)-CDF bucket-map table hoisted to a one-shot setup kernel (erfcf
// removed from the 8192 hot blocks).

static constexpr int D = 1571;
static constexpr int NB = 1024;
static constexpr int THREADS = 512;
static constexpr int NE = 512;  // octave-table entries (e = kk>>23, 9 bits)

__device__ unsigned g_base[NE + 1];

__global__ void build_base_kernel() {
  const int t = threadIdx.x;
  if (t <= NE) {
    unsigned b;
    if (t == NE) {
      b = NB;
    } else {
      const unsigned kk0 = (unsigned)t << 23;  // lower edge of octave band t
      const unsigned a = ~kk0;
      const unsigned u = (a & 0x80000000u) ? (a ^ 0x80000000u) : ~a;
      const float x = __uint_as_float(u);      // band edge value (+/-inf ok)
      const float c = 0.5f * erfcf(x * 0.70710678118f);  // P(N(0,1) > x)
      b = (unsigned)(c * (float)NB);
      if (b > NB - 1u) b = NB - 1u;
    }
    g_base[t] = b;
  }
}

__global__ void __launch_bounds__(THREADS) cutoutput_bucket_kernel(
    const float* __restrict__ to_cut,
    const int* __restrict__ candA,
    const int* __restrict__ candB,
    float* __restrict__ out) {
  __shared__ unsigned long long data[D];     // bucketed (kk<<11)|idx
  __shared__ unsigned base[NE + 1];          // bucket-map table (copied)
  __shared__ unsigned startb[NB + 1];        // bucket start offsets
  __shared__ unsigned hist[NB];              // counts
  __shared__ unsigned cursor[NB];            // scatter cursors
  __shared__ unsigned wsum[16];              // scan partials
  __shared__ unsigned short staged[D];       // rank -> idx

  const int t = threadIdx.x;
  const int row = blockIdx.x;
  const float* __restrict__ src = to_cut + (size_t)row * D;

  // ---- copy precomputed table; clear histogram ----
  if (t <= NE) base[t] = g_base[t];
  hist[t] = 0;
  hist[t + THREADS] = 0;
  __syncthreads();

  // ---- phase 1: load, key, bucket, histogram ----
  unsigned kks[4];
  unsigned short bks[4];
#pragma unroll
  for (int k = 0; k < 4; ++k) {
    const int v = t + k * THREADS;
    if (v < D) {
      const unsigned u = __float_as_uint(src[v]);
      const unsigned a = u ^ ((u & 0x80000000u) ? 0xFFFFFFFFu : 0x80000000u);
      const unsigned kk = ~a;                     // ascending kk == desc value
      const unsigned e = kk >> 23;
      const unsigned b0 = base[e];
      const unsigned n = base[e + 1] - b0;
      const unsigned m = (kk >> 7) & 0xFFFFu;
      const unsigned bk = b0 + ((m * n) >> 16);   // exact monotone in kk
      kks[k] = kk;
      bks[k] = (unsigned short)bk;
      atomicAdd(&hist[bk], 1u);
    }
  }
  __syncthreads();

  // ---- exclusive scan over NB=1024 buckets with 512 threads (2 each) ----
  {
    const unsigned h0 = hist[2 * t];
    const unsigned h1 = hist[2 * t + 1];
    const unsigned pair = h0 + h1;
    unsigned v = pair;
#pragma unroll
    for (int d = 1; d < 32; d <<= 1) {
      unsigned nbr = __shfl_up_sync(0xFFFFFFFFu, v, d);
      if ((t & 31) >= d) v += nbr;
    }
    if ((t & 31) == 31) wsum[t >> 5] = v;
    __syncthreads();
    if (t < 16) {
      unsigned w = wsum[t];
#pragma unroll
      for (int d = 1; d < 16; d <<= 1) {
        unsigned nbr = __shfl_up_sync(0xFFFFu, w, d);
        if (t >= d) w += nbr;
      }
      wsum[t] = w;
    }
    __syncthreads();
    const unsigned excl =
        v - pair + ((t >= 32) ? wsum[(t >> 5) - 1] : 0u);
    startb[2 * t] = excl;
    startb[2 * t + 1] = excl + h0;
    cursor[2 * t] = excl;
    cursor[2 * t + 1] = excl + h0;
    if (t == 0) startb[NB] = (unsigned)D;
  }
  __syncthreads();

  // ---- scatter packed keys into bucket regions ----
  unsigned long long mykey[4];
#pragma unroll
  for (int k = 0; k < 4; ++k) {
    const int v = t + k * THREADS;
    if (v < D) {
      const unsigned long long kv =
          ((unsigned long long)kks[k] << 11) | (unsigned)v;
      mykey[k] = kv;
      const unsigned pos = atomicAdd(&cursor[bks[k]], 1u);
      data[pos] = kv;
    }
  }
  __syncthreads();

  // ---- phase 2: per-ELEMENT rank within its bucket (key in register) ----
#pragma unroll
  for (int k = 0; k < 4; ++k) {
    const int v = t + k * THREADS;
    if (v < D) {
      const unsigned long long ki = mykey[k];
      const unsigned s = startb[bks[k]];
      const unsigned e = startb[bks[k] + 1];
      unsigned r = s;
      for (unsigned j = s; j < e; ++j) r += (data[j] < ki) ? 1u : 0u;
      staged[r] = (unsigned short)(v);
    }
  }
  __syncthreads();

  // ---- output: coalesced sweep with len mask ----
  // base vs ids disambiguation: ids[0] == 0 always; base[0] >= 1 always.
  const int* __restrict__ basep = (candA[0] == 0) ? candB : candA;
  const int len = basep[row];
  float* __restrict__ dst = out + (size_t)row * D;
#pragma unroll
  for (int k = 0; k < 4; ++k) {
    const int r = t + k * THREADS;
    if (r < D) dst[r] = (r < len) ? (float)staged[r] : 0.0f;
  }
}

extern "C" void kernel_launch(void* const* d_in, const int* in_sizes, int n_in,
                              void* d_out, int out_size) {
  // to_cut is the (unique) large buffer: P*T*D elements.
  int imax = 0;
  for (int i = 1; i < n_in; ++i)
    if (in_sizes[i] > in_sizes[imax]) imax = i;
  const float* to_cut = (const float*)d_in[imax];

  int others[2], k = 0;
  for (int i = 0; i < n_in && k < 2; ++i)
    if (i != imax) others[k++] = i;
  const int* candA = (const int*)d_in[others[0]];
  const int* candB = (const int*)d_in[others[1]];

  float* out = (float*)d_out;
  const int rows = in_sizes[imax] / D;  // P*T = 8192

  build_base_kernel<<<1, NE + 32>>>();
  cutoutput_bucket_kernel<<<rows, THREADS>>>(to_cut, candA, candB, out);
}

// round 7
// speedup vs baseline: 2.8793x; 1.0181x over previous
#include <cuda_runtime.h>
#include <cstdint>

// CutOutput: per-row (8192 rows) stable descending argsort of D=1571 fp32,
// out[row][r] = (float)index_at_rank_r if r < len else 0, len = base[row].
// Output float32. Stability required (packed-u64 idx tie-break on fp32 ties).
//
// R7 (L1-wavefront-bound per ncu):
//  * NB=2048 buckets (lambda=0.77): 46% of elements land in singleton buckets
//    -> no data[] write, no ranking loop for them.
//  * Fused ordering: hist atomicAdd's return value is the within-bucket
//    arrival order -> pos = startb[bk] + myord; cursor array + its 1571
//    atomics removed.
//  * Ranking still compares full (kk<<11)|idx u64 -> deterministic output
//    independent of atomic arrival order; == JAX stable argsort.

static constexpr int D = 1571;
static constexpr int NB = 2048;
static constexpr int THREADS = 512;
static constexpr int NE = 512;  // octave-table entries (e = kk>>23, 9 bits)

__device__ unsigned g_base[NE + 1];

__global__ void build_base_kernel() {
  const int t = threadIdx.x;
  if (t <= NE) {
    unsigned b;
    if (t == NE) {
      b = NB;
    } else {
      const unsigned kk0 = (unsigned)t << 23;  // lower edge of octave band t
      const unsigned a = ~kk0;
      const unsigned u = (a & 0x80000000u) ? (a ^ 0x80000000u) : ~a;
      const float x = __uint_as_float(u);      // band edge value (+/-inf ok)
      const float c = 0.5f * erfcf(x * 0.70710678118f);  // P(N(0,1) > x)
      b = (unsigned)(c * (float)NB);
      if (b > NB - 1u) b = NB - 1u;
    }
    g_base[t] = b;
  }
}

__global__ void __launch_bounds__(THREADS) cutoutput_bucket_kernel(
    const float* __restrict__ to_cut,
    const int* __restrict__ candA,
    const int* __restrict__ candB,
    float* __restrict__ out) {
  __shared__ unsigned long long data[D];     // bucketed (kk<<11)|idx (multi only)
  __shared__ unsigned base[NE + 1];          // bucket-map table (copied)
  __shared__ unsigned startb[NB + 1];        // bucket start offsets
  __shared__ unsigned hist[NB];              // counts (preserved after scan)
  __shared__ unsigned wsum[16];              // scan partials
  __shared__ unsigned short staged[D];       // rank -> idx

  const int t = threadIdx.x;
  const int row = blockIdx.x;
  const float* __restrict__ src = to_cut + (size_t)row * D;

  // ---- copy precomputed table; clear histogram ----
  if (t <= NE) base[t] = g_base[t];
#pragma unroll
  for (int k = 0; k < NB / THREADS; ++k) hist[t + k * THREADS] = 0;
  __syncthreads();

  // ---- phase 1: load, key, bucket, fused histogram+order ----
  unsigned kks[4];
  unsigned short bks[4];
  unsigned short ords[4];
#pragma unroll
  for (int k = 0; k < 4; ++k) {
    const int v = t + k * THREADS;
    if (v < D) {
      const unsigned u = __float_as_uint(src[v]);
      const unsigned a = u ^ ((u & 0x80000000u) ? 0xFFFFFFFFu : 0x80000000u);
      const unsigned kk = ~a;                     // ascending kk == desc value
      const unsigned e = kk >> 23;
      const unsigned b0 = base[e];
      const unsigned n = base[e + 1] - b0;
      const unsigned m = (kk >> 7) & 0xFFFFu;
      const unsigned bk = b0 + ((m * n) >> 16);   // exact monotone in kk
      kks[k] = kk;
      bks[k] = (unsigned short)bk;
      ords[k] = (unsigned short)atomicAdd(&hist[bk], 1u);  // arrival order
    }
  }
  __syncthreads();

  // ---- exclusive scan over NB=2048 buckets (4 per thread) ----
  {
    unsigned h[4];
    unsigned sum = 0;
#pragma unroll
    for (int k = 0; k < 4; ++k) {
      h[k] = hist[4 * t + k];
      sum += h[k];
    }
    unsigned v = sum;
#pragma unroll
    for (int d = 1; d < 32; d <<= 1) {
      unsigned nbr = __shfl_up_sync(0xFFFFFFFFu, v, d);
      if ((t & 31) >= d) v += nbr;
    }
    if ((t & 31) == 31) wsum[t >> 5] = v;
    __syncthreads();
    if (t < 16) {
      unsigned w = wsum[t];
#pragma unroll
      for (int d = 1; d < 16; d <<= 1) {
        unsigned nbr = __shfl_up_sync(0xFFFFu, w, d);
        if (t >= d) w += nbr;
      }
      wsum[t] = w;
    }
    __syncthreads();
    unsigned excl = v - sum + ((t >= 32) ? wsum[(t >> 5) - 1] : 0u);
#pragma unroll
    for (int k = 0; k < 4; ++k) {
      startb[4 * t + k] = excl;
      excl += h[k];
    }
    if (t == 0) startb[NB] = (unsigned)D;
  }
  __syncthreads();

  // ---- scatter (multi-element buckets only); singleton fast path ----
#pragma unroll
  for (int k = 0; k < 4; ++k) {
    const int v = t + k * THREADS;
    if (v < D) {
      const unsigned bk = bks[k];
      const unsigned s = startb[bk];
      if (hist[bk] == 1u) {
        staged[s] = (unsigned short)v;     // rank known: bucket of one
        bks[k] = 0xFFFFu;                  // mark done
      } else {
        data[s + ords[k]] = ((unsigned long long)kks[k] << 11) | (unsigned)v;
      }
    }
  }
  __syncthreads();

  // ---- phase 2: per-element rank within multi-element buckets ----
#pragma unroll
  for (int k = 0; k < 4; ++k) {
    const int v = t + k * THREADS;
    if (v < D && bks[k] != 0xFFFFu) {
      const unsigned bk = bks[k];
      const unsigned s = startb[bk];
      const unsigned e = s + hist[bk];
      const unsigned long long ki =
          ((unsigned long long)kks[k] << 11) | (unsigned)v;
      unsigned r = s;
      for (unsigned j = s; j < e; ++j) r += (data[j] < ki) ? 1u : 0u;
      staged[r] = (unsigned short)v;
    }
  }
  __syncthreads();

  // ---- output: coalesced sweep with len mask ----
  // base vs ids disambiguation: ids[0] == 0 always; base[0] >= 1 always.
  const int* __restrict__ basep = (candA[0] == 0) ? candB : candA;
  const int len = basep[row];
  float* __restrict__ dst = out + (size_t)row * D;
#pragma unroll
  for (int k = 0; k < 4; ++k) {
    const int r = t + k * THREADS;
    if (r < D) dst[r] = (r < len) ? (float)staged[r] : 0.0f;
  }
}

extern "C" void kernel_launch(void* const* d_in, const int* in_sizes, int n_in,
                              void* d_out, int out_size) {
  // to_cut is the (unique) large buffer: P*T*D elements.
  int imax = 0;
  for (int i = 1; i < n_in; ++i)
    if (in_sizes[i] > in_sizes[imax]) imax = i;
  const float* to_cut = (const float*)d_in[imax];

  int others[2], k = 0;
  for (int i = 0; i < n_in && k < 2; ++i)
    if (i != imax) others[k++] = i;
  const int* candA = (const int*)d_in[others[0]];
  const int* candB = (const int*)d_in[others[1]];

  float* out = (float*)d_out;
  const int rows = in_sizes[imax] / D;  // P*T = 8192

  build_base_kernel<<<1, NE + 32>>>();
  cutoutput_bucket_kernel<<<rows, THREADS>>>(to_cut, candA, candB, out);
}

// round 8
// speedup vs baseline: 2.8869x; 1.0026x over previous
#include <cuda_runtime.h>
#include <cstdint>

// CutOutput: per-row (8192 rows) stable descending argsort of D=1571 fp32,
// out[row][r] = (float)index_at_rank_r if r < len else 0, len = base[row].
// Output float32. Stability via packed-u64 (kk<<11)|idx tie-break.
//
// R8 (L1-wavefront-bound, fixed costs dominate): LEN-AWARE PRUNING.
// Ranks == bucket order, len ~ Uniform[1, D-1] (mean D/2): any bucket with
// startb[bk] >= len emits only zeros -> skip its scatter, data[] write,
// ranking, and staged write entirely (~50% of that work deleted on average).
// Histogram+scan stay full (live buckets' offsets depend only on lower==live
// buckets, so the cut is exact). Straddling buckets rank fully.

static constexpr int D = 1571;
static constexpr int NB = 2048;
static constexpr int THREADS = 512;
static constexpr int NE = 512;  // octave-table entries (e = kk>>23, 9 bits)

__device__ unsigned g_base[NE + 1];

__global__ void build_base_kernel() {
  const int t = threadIdx.x;
  if (t <= NE) {
    unsigned b;
    if (t == NE) {
      b = NB;
    } else {
      const unsigned kk0 = (unsigned)t << 23;  // lower edge of octave band t
      const unsigned a = ~kk0;
      const unsigned u = (a & 0x80000000u) ? (a ^ 0x80000000u) : ~a;
      const float x = __uint_as_float(u);      // band edge value (+/-inf ok)
      const float c = 0.5f * erfcf(x * 0.70710678118f);  // P(N(0,1) > x)
      b = (unsigned)(c * (float)NB);
      if (b > NB - 1u) b = NB - 1u;
    }
    g_base[t] = b;
  }
}

__global__ void __launch_bounds__(THREADS) cutoutput_bucket_kernel(
    const float* __restrict__ to_cut,
    const int* __restrict__ candA,
    const int* __restrict__ candB,
    float* __restrict__ out) {
  __shared__ unsigned long long data[D];     // bucketed (kk<<11)|idx (live multi)
  __shared__ unsigned base[NE + 1];          // bucket-map table (copied)
  __shared__ unsigned startb[NB + 1];        // bucket start offsets
  __shared__ unsigned hist[NB];              // counts (preserved after scan)
  __shared__ unsigned wsum[16];              // scan partials
  __shared__ unsigned short staged[D];       // rank -> idx (only [0,len) used)

  const int t = threadIdx.x;
  const int row = blockIdx.x;
  const float* __restrict__ src = to_cut + (size_t)row * D;

  // base vs ids disambiguation: ids[0] == 0 always; base[0] >= 1 always.
  const int* __restrict__ basep = (candA[0] == 0) ? candB : candA;
  const unsigned len = (unsigned)basep[row];

  // ---- copy precomputed table; clear histogram ----
  if (t <= NE) base[t] = g_base[t];
#pragma unroll
  for (int k = 0; k < NB / THREADS; ++k) hist[t + k * THREADS] = 0;
  __syncthreads();

  // ---- phase 1: load, key, bucket, fused histogram+order ----
  unsigned kks[4];
  unsigned short bks[4];
  unsigned short ords[4];
#pragma unroll
  for (int k = 0; k < 4; ++k) {
    const int v = t + k * THREADS;
    if (v < D) {
      const unsigned u = __float_as_uint(src[v]);
      const unsigned a = u ^ ((u & 0x80000000u) ? 0xFFFFFFFFu : 0x80000000u);
      const unsigned kk = ~a;                     // ascending kk == desc value
      const unsigned e = kk >> 23;
      const unsigned b0 = base[e];
      const unsigned n = base[e + 1] - b0;
      const unsigned m = (kk >> 7) & 0xFFFFu;
      const unsigned bk = b0 + ((m * n) >> 16);   // exact monotone in kk
      kks[k] = kk;
      bks[k] = (unsigned short)bk;
      ords[k] = (unsigned short)atomicAdd(&hist[bk], 1u);  // arrival order
    }
  }
  __syncthreads();

  // ---- exclusive scan over NB=2048 buckets (4 per thread) ----
  {
    unsigned h[4];
    unsigned sum = 0;
#pragma unroll
    for (int k = 0; k < 4; ++k) {
      h[k] = hist[4 * t + k];
      sum += h[k];
    }
    unsigned v = sum;
#pragma unroll
    for (int d = 1; d < 32; d <<= 1) {
      unsigned nbr = __shfl_up_sync(0xFFFFFFFFu, v, d);
      if ((t & 31) >= d) v += nbr;
    }
    if ((t & 31) == 31) wsum[t >> 5] = v;
    __syncthreads();
    if (t < 16) {
      unsigned w = wsum[t];
#pragma unroll
      for (int d = 1; d < 16; d <<= 1) {
        unsigned nbr = __shfl_up_sync(0xFFFFu, w, d);
        if (t >= d) w += nbr;
      }
      wsum[t] = w;
    }
    __syncthreads();
    unsigned excl = v - sum + ((t >= 32) ? wsum[(t >> 5) - 1] : 0u);
#pragma unroll
    for (int k = 0; k < 4; ++k) {
      startb[4 * t + k] = excl;
      excl += h[k];
    }
    if (t == 0) startb[NB] = (unsigned)D;
  }
  __syncthreads();

  // ---- scatter: only LIVE buckets (startb < len); singleton fast path ----
#pragma unroll
  for (int k = 0; k < 4; ++k) {
    const int v = t + k * THREADS;
    if (v < D) {
      const unsigned bk = bks[k];
      const unsigned s = startb[bk];
      if (s >= len) {
        bks[k] = 0xFFFFu;                  // dead bucket: output is 0 anyway
      } else if (hist[bk] == 1u) {
        staged[s] = (unsigned short)v;     // rank known: bucket of one
        bks[k] = 0xFFFFu;
      } else {
        data[s + ords[k]] = ((unsigned long long)kks[k] << 11) | (unsigned)v;
      }
    }
  }
  __syncthreads();

  // ---- phase 2: per-element rank within live multi-element buckets ----
#pragma unroll
  for (int k = 0; k < 4; ++k) {
    const int v = t + k * THREADS;
    if (v < D && bks[k] != 0xFFFFu) {
      const unsigned bk = bks[k];
      const unsigned s = startb[bk];
      const unsigned e = s + hist[bk];
      const unsigned long long ki =
          ((unsigned long long)kks[k] << 11) | (unsigned)v;
      unsigned r = s;
      for (unsigned j = s; j < e; ++j) r += (data[j] < ki) ? 1u : 0u;
      if (r < len) staged[r] = (unsigned short)v;
    }
  }
  __syncthreads();

  // ---- output: coalesced sweep with len mask ----
  float* __restrict__ dst = out + (size_t)row * D;
#pragma unroll
  for (int k = 0; k < 4; ++k) {
    const unsigned r = (unsigned)(t + k * THREADS);
    if (r < D) dst[r] = (r < len) ? (float)staged[r] : 0.0f;
  }
}

extern "C" void kernel_launch(void* const* d_in, const int* in_sizes, int n_in,
                              void* d_out, int out_size) {
  // to_cut is the (unique) large buffer: P*T*D elements.
  int imax = 0;
  for (int i = 1; i < n_in; ++i)
    if (in_sizes[i] > in_sizes[imax]) imax = i;
  const float* to_cut = (const float*)d_in[imax];

  int others[2], k = 0;
  for (int i = 0; i < n_in && k < 2; ++i)
    if (i != imax) others[k++] = i;
  const int* candA = (const int*)d_in[others[0]];
  const int* candB = (const int*)d_in[others[1]];

  float* out = (float*)d_out;
  const int rows = in_sizes[imax] / D;  // P*T = 8192

  build_base_kernel<<<1, NE + 32>>>();
  cutoutput_bucket_kernel<<<rows, THREADS>>>(to_cut, candA, candB, out);
}